// round 11
// baseline (speedup 1.0000x reference)
#include <cuda_runtime.h>

#define B_WIN 2048
#define NTOK  98
#define NHEAD 4
#define HD    32
#define C3    384
#define DIMM  128
#define NWIN  64
#define NN    (NTOK * NTOK)   // 9604
#define RPB_ROWS 507

typedef unsigned int uint;

// ---------------- bf16 helpers ----------------
__device__ __forceinline__ uint pkbf(float lo, float hi) {
    uint r; asm("cvt.rn.bf16x2.f32 %0, %1, %2;" : "=r"(r) : "f"(hi), "f"(lo)); return r;
}
__device__ __forceinline__ float blo(uint p) { return __uint_as_float(p << 16); }
__device__ __forceinline__ float bhi(uint p) { return __uint_as_float(p & 0xffff0000u); }

// D += A * B  (m16n8k16, bf16 in, f32 accum)
__device__ __forceinline__ void mma16816(float* d, const uint* a, uint b0, uint b1) {
    asm("mma.sync.aligned.m16n8k16.row.col.f32.bf16.bf16.f32 "
        "{%0,%1,%2,%3}, {%4,%5,%6,%7}, {%8,%9}, {%0,%1,%2,%3};"
        : "+f"(d[0]), "+f"(d[1]), "+f"(d[2]), "+f"(d[3])
        : "r"(a[0]), "r"(a[1]), "r"(a[2]), "r"(a[3]), "r"(b0), "r"(b1));
}

// ldmatrix x4
__device__ __forceinline__ void ldm4(uint* d, uint addr) {
    asm volatile("ldmatrix.sync.aligned.m8n8.x4.shared.b16 {%0,%1,%2,%3}, [%4];"
        : "=r"(d[0]), "=r"(d[1]), "=r"(d[2]), "=r"(d[3]) : "r"(addr));
}

// ---------------- scratch ----------------
__device__ float g_bm[(size_t)NWIN * NHEAD * NN];   // bias + mask (fp32), 9.8 MB
__device__ uint  g_th[(size_t)B_WIN * NTOK * 64];   // attn out hi (bf16x2), 51.4 MB
__device__ uint  g_tl[(size_t)B_WIN * NTOK * 64];   // attn out lo (bf16x2), 51.4 MB

// smem word offsets (attention kernel)
#define QH  0
#define QL  2240
#define KH  4480
#define KL  6720
#define VTH 8960
#define VTL 10880
#define QKVW 12800     // 51200 B
// smem word offsets (projection kernel)
#define WH  0
#define WL  8704
#define PRJW 17408     // 69632 B

// ---------------------------------------------------------------------------
// Kernel A: g_bm[w][h][q*98+k] = rpb_table[rpi[q,k]][h] + mask[w][q][k]
// ---------------------------------------------------------------------------
__global__ void bm_kernel(const int* __restrict__ rpi,
                          const float* __restrict__ table,
                          const float* __restrict__ mask) {
    int i = blockIdx.x * blockDim.x + threadIdx.x;
    if (i >= NWIN * NN) return;
    int w = i / NN;
    int e = i - w * NN;
    int r = rpi[e];
    r = (r < 0) ? 0 : (r >= RPB_ROWS ? RPB_ROWS - 1 : r);
    float mk = mask[(size_t)w * NN + e];
#pragma unroll
    for (int hh = 0; hh < NHEAD; hh++) {
        g_bm[((size_t)w * NHEAD + hh) * NN + e] = table[r * NHEAD + hh] + mk;
    }
}

// ---------------------------------------------------------------------------
// Attention kernel: one (head, window) per CTA. Streaming softmax-deferred,
// LDSM operands, bf16x3 compensated MMA. 256 threads, small register set.
// ---------------------------------------------------------------------------
__global__ __launch_bounds__(256, 4) void attn_kernel(const float* __restrict__ x) {
    extern __shared__ uint smw[];

    const int h   = blockIdx.x;
    const int b   = blockIdx.y;
    const int tid = threadIdx.x;
    const int lane = tid & 31;
    const int wid  = tid >> 5;
    const int g = lane >> 2;
    const int t = lane & 3;
    const int l7 = lane & 7;

    const float scale = 0.17677669529663687f;  // 1/sqrt(32)
    const float* xb = x + (size_t)b * NTOK * C3;
    const int r0 = wid * 16 + g;
    const int q1 = r0 + 8;
    const bool rok0 = (r0 < NTOK), rok1 = (q1 < NTOK);

    // ---- per-lane ldmatrix base addresses ----
    const uint qbase = (uint)__cvta_generic_to_shared(
        smw + QH + (wid * 16 + ((lane >> 3) & 1) * 8 + l7) * 20) + (lane >> 4) * 16;
    const uint kbase = (uint)__cvta_generic_to_shared(
        smw + ((lane < 16) ? KH : KL) + l7 * 20) + ((lane >> 3) & 1) * 16;
    const uint vbase = (uint)__cvta_generic_to_shared(
        smw + ((lane < 16) ? VTH : VTL) + l7 * 60) + ((lane >> 3) & 1) * 16;

    // ---- zero QKV region (covers all row/col pads) ----
    for (int i = tid; i < QKVW; i += 256) smw[i] = 0u;
    __syncthreads();

    // ---- load + split Q(scaled), K, V(transposed) to bf16 hi/lo ----
    for (int i = tid; i < NTOK * 16; i += 256) {
        int q = i >> 4, dp = i & 15;
        const float* base = xb + q * C3 + h * HD + 2 * dp;
        float2 qv = *(const float2*)base;
        qv.x *= scale; qv.y *= scale;
        uint hq = pkbf(qv.x, qv.y);
        smw[QH + q * 20 + dp] = hq;
        smw[QL + q * 20 + dp] = pkbf(qv.x - blo(hq), qv.y - bhi(hq));
        float2 kv = *(const float2*)(base + DIMM);
        uint hk = pkbf(kv.x, kv.y);
        smw[KH + q * 20 + dp] = hk;
        smw[KL + q * 20 + dp] = pkbf(kv.x - blo(hk), kv.y - bhi(hk));
        float2 vv = *(const float2*)(base + 2 * DIMM);
        uint hv = pkbf(vv.x, vv.y);
        uint lv = pkbf(vv.x - blo(hv), vv.y - bhi(hv));
        unsigned short* vth = (unsigned short*)(smw + VTH);
        unsigned short* vtl = (unsigned short*)(smw + VTL);
        int d0 = 2 * dp;
        vth[d0 * 120 + q]       = (unsigned short)(hv & 0xffffu);
        vth[(d0 + 1) * 120 + q] = (unsigned short)(hv >> 16);
        vtl[d0 * 120 + q]       = (unsigned short)(lv & 0xffffu);
        vtl[(d0 + 1) * 120 + q] = (unsigned short)(lv >> 16);
    }
    __syncthreads();

    if (wid >= 7) return;

    const float* bmp = g_bm + ((size_t)(b & (NWIN - 1)) * NHEAD + h) * NN;
    float s0 = 0.0f, s1 = 0.0f;
    float Oh[16];
#pragma unroll
    for (int j = 0; j < 16; j++) Oh[j] = 0.0f;

    // ---- stream over k16 chunks: S pair -> exp -> pack -> PV ----
#pragma unroll
    for (int c = 0; c < 7; c++) {
        float Sp[2][4];
#pragma unroll
        for (int u = 0; u < 2; u++)
#pragma unroll
            for (int j = 0; j < 4; j++) Sp[u][j] = 0.0f;

#pragma unroll
        for (int s = 0; s < 2; s++) {
            uint kf0[4], kf1[4], qh_[4], ql_[4];
            ldm4(kf0, kbase + (2 * c) * 640 + s * 32);
            ldm4(kf1, kbase + (2 * c + 1) * 640 + s * 32);
            ldm4(qh_, qbase + s * 32);
            ldm4(ql_, qbase + 8960 + s * 32);   // QL region (+2240 words)
            mma16816(Sp[0], qh_, kf0[0], kf0[1]);
            mma16816(Sp[1], qh_, kf1[0], kf1[1]);
            mma16816(Sp[0], qh_, kf0[2], kf0[3]);
            mma16816(Sp[1], qh_, kf1[2], kf1[3]);
            mma16816(Sp[0], ql_, kf0[0], kf0[1]);
            mma16816(Sp[1], ql_, kf1[0], kf1[1]);
        }

        // ---- bias + mask + padding, then exp (no max subtract) ----
#pragma unroll
        for (int u = 0; u < 2; u++) {
            int nt = 2 * c + u;
            int c0 = nt * 8 + 2 * t;
            bool cok = (c0 < NTOK);
            if (rok0 && cok) {
                float2 bb = __ldg((const float2*)(bmp + r0 * NTOK + c0));
                Sp[u][0] += bb.x; Sp[u][1] += bb.y;
            } else { Sp[u][0] = -1e30f; Sp[u][1] = -1e30f; }
            if (rok1 && cok) {
                float2 bb = __ldg((const float2*)(bmp + q1 * NTOK + c0));
                Sp[u][2] += bb.x; Sp[u][3] += bb.y;
            } else { Sp[u][2] = -1e30f; Sp[u][3] = -1e30f; }
            Sp[u][0] = __expf(Sp[u][0]); s0 += Sp[u][0];
            Sp[u][1] = __expf(Sp[u][1]); s0 += Sp[u][1];
            Sp[u][2] = __expf(Sp[u][2]); s1 += Sp[u][2];
            Sp[u][3] = __expf(Sp[u][3]); s1 += Sp[u][3];
        }

        // ---- pack unnormalized P to bf16 hi/lo A-fragment ----
        uint pah[4], pal[4];
        pah[0] = pkbf(Sp[0][0], Sp[0][1]);
        pal[0] = pkbf(Sp[0][0] - blo(pah[0]), Sp[0][1] - bhi(pah[0]));
        pah[1] = pkbf(Sp[0][2], Sp[0][3]);
        pal[1] = pkbf(Sp[0][2] - blo(pah[1]), Sp[0][3] - bhi(pah[1]));
        pah[2] = pkbf(Sp[1][0], Sp[1][1]);
        pal[2] = pkbf(Sp[1][0] - blo(pah[2]), Sp[1][1] - bhi(pah[2]));
        pah[3] = pkbf(Sp[1][2], Sp[1][3]);
        pal[3] = pkbf(Sp[1][2] - blo(pah[3]), Sp[1][3] - bhi(pah[3]));

        // ---- PV accumulate: 4 d-tiles, variant-major (4 chains) ----
        uint vf[4][4];
#pragma unroll
        for (int nt = 0; nt < 4; nt++)
            ldm4(vf[nt], vbase + nt * 1920 + c * 32);
#pragma unroll
        for (int nt = 0; nt < 4; nt++)
            mma16816(&Oh[4 * nt], pah, vf[nt][0], vf[nt][1]);
#pragma unroll
        for (int nt = 0; nt < 4; nt++)
            mma16816(&Oh[4 * nt], pah, vf[nt][2], vf[nt][3]);
#pragma unroll
        for (int nt = 0; nt < 4; nt++)
            mma16816(&Oh[4 * nt], pal, vf[nt][0], vf[nt][1]);
    }

    // ---- deferred normalization ----
    s0 += __shfl_xor_sync(0xffffffffu, s0, 1);
    s0 += __shfl_xor_sync(0xffffffffu, s0, 2);
    s1 += __shfl_xor_sync(0xffffffffu, s1, 1);
    s1 += __shfl_xor_sync(0xffffffffu, s1, 2);
    float inv0 = __frcp_rn(s0), inv1 = __frcp_rn(s1);

    // ---- store O as bf16 hi/lo pairs ----
    const size_t obase = (size_t)b * NTOK * 64 + h * 16;
#pragma unroll
    for (int nt = 0; nt < 4; nt++) {
        int dw = nt * 4 + t;
        if (rok0) {
            float f0 = Oh[4 * nt + 0] * inv0, f1 = Oh[4 * nt + 1] * inv0;
            uint hw_ = pkbf(f0, f1);
            g_th[obase + (size_t)r0 * 64 + dw] = hw_;
            g_tl[obase + (size_t)r0 * 64 + dw] = pkbf(f0 - blo(hw_), f1 - bhi(hw_));
        }
        if (rok1) {
            float f2 = Oh[4 * nt + 2] * inv1, f3 = Oh[4 * nt + 3] * inv1;
            uint hw_ = pkbf(f2, f3);
            g_th[obase + (size_t)q1 * 64 + dw] = hw_;
            g_tl[obase + (size_t)q1 * 64 + dw] = pkbf(f2 - blo(hw_), f3 - bhi(hw_));
        }
    }
}

// ---------------------------------------------------------------------------
// Projection kernel: out[r][c] = sum_d A[r][d] * W[c][d] + pb[c]
// A = g_th/g_tl (bf16 hi/lo) via LDG; W split in smem via LDSM. 128 rows/block.
// ---------------------------------------------------------------------------
__global__ __launch_bounds__(256, 3) void proj_kernel(const float* __restrict__ pw,
                                                      const float* __restrict__ pb,
                                                      float* __restrict__ out) {
    extern __shared__ uint ws[];
    const int tid = threadIdx.x;
    const int lane = tid & 31;
    const int wid  = tid >> 5;
    const int g = lane >> 2, t = lane & 3;
    const int l7 = lane & 7;

    // load + split W: Wh/Wl [128 cols x 68w stride]
    for (int i = tid; i < 8192; i += 256) {
        int c = i >> 6, dp = i & 63;
        float2 w = *(const float2*)(pw + c * DIMM + 2 * dp);
        uint hw_ = pkbf(w.x, w.y);
        ws[WH + c * 68 + dp] = hw_;
        ws[WL + c * 68 + dp] = pkbf(w.x - blo(hw_), w.y - bhi(hw_));
    }
    __syncthreads();

    const uint wbase = (uint)__cvta_generic_to_shared(
        ws + ((lane < 16) ? WH : WL) + l7 * 68) + ((lane >> 3) & 1) * 16;

    const size_t r0 = (size_t)blockIdx.x * 128 + wid * 16 + g;
    const size_t r1 = r0 + 8;
    float* orow0 = out + r0 * DIMM;
    float* orow1 = out + r1 * DIMM;

#pragma unroll
    for (int half = 0; half < 2; half++) {
        float R[8][4];
#pragma unroll
        for (int nt = 0; nt < 8; nt++)
#pragma unroll
            for (int j = 0; j < 4; j++) R[nt][j] = 0.0f;

#pragma unroll
        for (int s = 0; s < 8; s++) {
            uint ah[4], al[4];
            ah[0] = g_th[r0 * 64 + 8 * s + t];
            ah[1] = g_th[r1 * 64 + 8 * s + t];
            ah[2] = g_th[r0 * 64 + 8 * s + t + 4];
            ah[3] = g_th[r1 * 64 + 8 * s + t + 4];
            al[0] = g_tl[r0 * 64 + 8 * s + t];
            al[1] = g_tl[r1 * 64 + 8 * s + t];
            al[2] = g_tl[r0 * 64 + 8 * s + t + 4];
            al[3] = g_tl[r1 * 64 + 8 * s + t + 4];
#pragma unroll
            for (int grp = 0; grp < 2; grp++) {
                uint wf[4][4];
#pragma unroll
                for (int i = 0; i < 4; i++)
                    ldm4(wf[i], wbase + (half * 8 + grp * 4 + i) * 2176 + s * 32);
#pragma unroll
                for (int i = 0; i < 4; i++)
                    mma16816(R[grp * 4 + i], ah, wf[i][0], wf[i][1]);
#pragma unroll
                for (int i = 0; i < 4; i++)
                    mma16816(R[grp * 4 + i], ah, wf[i][2], wf[i][3]);
#pragma unroll
                for (int i = 0; i < 4; i++)
                    mma16816(R[grp * 4 + i], al, wf[i][0], wf[i][1]);
            }
        }

#pragma unroll
        for (int nt = 0; nt < 8; nt++) {
            int c0 = (half * 8 + nt) * 8 + 2 * t;
            float2 bb = __ldg((const float2*)(pb + c0));
            float2 o0 = { R[nt][0] + bb.x, R[nt][1] + bb.y };
            float2 o1 = { R[nt][2] + bb.x, R[nt][3] + bb.y };
            *(float2*)(orow0 + c0) = o0;
            *(float2*)(orow1 + c0) = o1;
        }
    }
}

// ---------------------------------------------------------------------------
extern "C" void kernel_launch(void* const* d_in, const int* in_sizes, int n_in,
                              void* d_out, int out_size) {
    const float* x     = (const float*)d_in[0];
    const int*   rpi   = (const int*)d_in[1];      // int32 on the wire
    const float* mask  = (const float*)d_in[2];
    const float* table = (const float*)d_in[3];
    const float* pw    = (const float*)d_in[4];
    const float* pb    = (const float*)d_in[5];
    float*       out   = (float*)d_out;

    const int smem_attn = QKVW * 4;   // 51200 B
    const int smem_proj = PRJW * 4;   // 69632 B
    cudaFuncSetAttribute(attn_kernel, cudaFuncAttributeMaxDynamicSharedMemorySize, smem_attn);
    cudaFuncSetAttribute(proj_kernel, cudaFuncAttributeMaxDynamicSharedMemorySize, smem_proj);

    bm_kernel<<<(NWIN * NN + 255) / 256, 256>>>(rpi, table, mask);
    attn_kernel<<<dim3(NHEAD, B_WIN), 256, smem_attn>>>(x);
    proj_kernel<<<(B_WIN * NTOK) / DIMM, 256, smem_proj>>>(pw, pb, out);
}

// round 12
// speedup vs baseline: 1.0406x; 1.0406x over previous
#include <cuda_runtime.h>

#define B_WIN 2048
#define NTOK  98
#define NHEAD 4
#define HD    32
#define C3    384
#define DIMM  128
#define NWIN  64
#define NN    (NTOK * NTOK)   // 9604
#define RPB_ROWS 507

typedef unsigned int uint;

// ---------------- bf16 helpers ----------------
__device__ __forceinline__ uint pkbf(float lo, float hi) {
    uint r; asm("cvt.rn.bf16x2.f32 %0, %1, %2;" : "=r"(r) : "f"(hi), "f"(lo)); return r;
}
__device__ __forceinline__ float blo(uint p) { return __uint_as_float(p << 16); }
__device__ __forceinline__ float bhi(uint p) { return __uint_as_float(p & 0xffff0000u); }

// D += A * B  (m16n8k16, bf16 in, f32 accum)
__device__ __forceinline__ void mma16816(float* d, const uint* a, uint b0, uint b1) {
    asm("mma.sync.aligned.m16n8k16.row.col.f32.bf16.bf16.f32 "
        "{%0,%1,%2,%3}, {%4,%5,%6,%7}, {%8,%9}, {%0,%1,%2,%3};"
        : "+f"(d[0]), "+f"(d[1]), "+f"(d[2]), "+f"(d[3])
        : "r"(a[0]), "r"(a[1]), "r"(a[2]), "r"(a[3]), "r"(b0), "r"(b1));
}

// ldmatrix x4
__device__ __forceinline__ void ldm4(uint* d, uint addr) {
    asm volatile("ldmatrix.sync.aligned.m8n8.x4.shared.b16 {%0,%1,%2,%3}, [%4];"
        : "=r"(d[0]), "=r"(d[1]), "=r"(d[2]), "=r"(d[3]) : "r"(addr));
}

// ---------------- scratch ----------------
__device__ float g_bm[(size_t)NWIN * NHEAD * NN];   // bias + mask (fp32), 9.8 MB

// smem word offsets, attention phase
#define QH  0
#define QL  2240
#define KH  4480
#define KL  6720
#define VTH 8960
#define VTL 10880
#define QKVW 12800
// O buffer (persists across both phases): 112 rows x 132-word stride
//   hi at word 0..63 of each row, lo at word 64..127
#define OS  12800
#define OSS 132
#define SMW_TOT (OS + 112 * OSS)   // 27584 words = 110336 B
// projection phase W chunk (overlays QKV region): 64 cols x 68-word stride, hi + lo
#define WCLO 4352                  // lo offset within W chunk region

// ---------------------------------------------------------------------------
// Kernel A: g_bm[w][h][q*98+k] = rpb_table[rpi[q,k]][h] + mask[w][q][k]
// ---------------------------------------------------------------------------
__global__ void bm_kernel(const int* __restrict__ rpi,
                          const float* __restrict__ table,
                          const float* __restrict__ mask) {
    int i = blockIdx.x * blockDim.x + threadIdx.x;
    if (i >= NWIN * NN) return;
    int w = i / NN;
    int e = i - w * NN;
    int r = rpi[e];
    r = (r < 0) ? 0 : (r >= RPB_ROWS ? RPB_ROWS - 1 : r);
    float mk = mask[(size_t)w * NN + e];
#pragma unroll
    for (int hh = 0; hh < NHEAD; hh++) {
        g_bm[((size_t)w * NHEAD + hh) * NN + e] = table[r * NHEAD + hh] + mk;
    }
}

// ---------------------------------------------------------------------------
// Fused v2: per window. 4 heads of streaming attention (O -> smem bf16 hi/lo),
// then projection from smem via LDSM with W streamed in 2 column chunks.
// 256 threads, 8 warps (warps 0-6 compute; warp 7 load/barrier only).
// ---------------------------------------------------------------------------
__global__ __launch_bounds__(256, 2) void fused_kernel(const float* __restrict__ x,
                                                       const float* __restrict__ pw,
                                                       const float* __restrict__ pb,
                                                       float* __restrict__ out) {
    extern __shared__ uint smw[];

    const int b   = blockIdx.x;
    const int tid = threadIdx.x;
    const int lane = tid & 31;
    const int wid  = tid >> 5;
    const int g = lane >> 2;
    const int t = lane & 3;
    const int l7 = lane & 7;

    const float scale = 0.17677669529663687f;  // 1/sqrt(32)
    const float* xb = x + (size_t)b * NTOK * C3;
    const int r0 = wid * 16 + g;
    const int q1 = r0 + 8;
    const bool rok0 = (r0 < NTOK), rok1 = (q1 < NTOK);

    // ---- per-lane ldmatrix base addresses (attention phase) ----
    const uint qbase = (uint)__cvta_generic_to_shared(
        smw + QH + (wid * 16 + ((lane >> 3) & 1) * 8 + l7) * 20) + (lane >> 4) * 16;
    const uint kbase = (uint)__cvta_generic_to_shared(
        smw + ((lane < 16) ? KH : KL) + l7 * 20) + ((lane >> 3) & 1) * 16;
    const uint vbase = (uint)__cvta_generic_to_shared(
        smw + ((lane < 16) ? VTH : VTL) + l7 * 60) + ((lane >> 3) & 1) * 16;
    // A fragments from Os (projection phase): hi at +0, lo at +256 bytes
    const uint abase = (uint)__cvta_generic_to_shared(
        smw + OS + (wid * 16 + ((lane >> 3) & 1) * 8 + l7) * OSS) + (lane >> 4) * 16;

    // ---- zero everything once (QKV pads + Os invalid rows) ----
    for (int i = tid; i < SMW_TOT; i += 256) smw[i] = 0u;
    __syncthreads();

#pragma unroll
    for (int h = 0; h < NHEAD; h++) {
        // ---- load + split Q(scaled), K, V(transposed) to bf16 hi/lo ----
        for (int i = tid; i < NTOK * 16; i += 256) {
            int q = i >> 4, dp = i & 15;
            const float* base = xb + q * C3 + h * HD + 2 * dp;
            float2 qv = *(const float2*)base;
            qv.x *= scale; qv.y *= scale;
            uint hq = pkbf(qv.x, qv.y);
            smw[QH + q * 20 + dp] = hq;
            smw[QL + q * 20 + dp] = pkbf(qv.x - blo(hq), qv.y - bhi(hq));
            float2 kv = *(const float2*)(base + DIMM);
            uint hk = pkbf(kv.x, kv.y);
            smw[KH + q * 20 + dp] = hk;
            smw[KL + q * 20 + dp] = pkbf(kv.x - blo(hk), kv.y - bhi(hk));
            float2 vv = *(const float2*)(base + 2 * DIMM);
            uint hv = pkbf(vv.x, vv.y);
            uint lv = pkbf(vv.x - blo(hv), vv.y - bhi(hv));
            unsigned short* vth = (unsigned short*)(smw + VTH);
            unsigned short* vtl = (unsigned short*)(smw + VTL);
            int d0 = 2 * dp;
            vth[d0 * 120 + q]       = (unsigned short)(hv & 0xffffu);
            vth[(d0 + 1) * 120 + q] = (unsigned short)(hv >> 16);
            vtl[d0 * 120 + q]       = (unsigned short)(lv & 0xffffu);
            vtl[(d0 + 1) * 120 + q] = (unsigned short)(lv >> 16);
        }
        __syncthreads();

        if (wid < 7) {
            const float* bmp = g_bm + ((size_t)(b & (NWIN - 1)) * NHEAD + h) * NN;
            float s0 = 0.0f, s1 = 0.0f;
            float Oh[16];
#pragma unroll
            for (int j = 0; j < 16; j++) Oh[j] = 0.0f;

            // ---- stream over k16 chunks: S pair -> exp -> pack -> PV ----
#pragma unroll
            for (int c = 0; c < 7; c++) {
                float Sp[2][4];
#pragma unroll
                for (int u = 0; u < 2; u++)
#pragma unroll
                    for (int j = 0; j < 4; j++) Sp[u][j] = 0.0f;

#pragma unroll
                for (int s = 0; s < 2; s++) {
                    uint kf0[4], kf1[4], qh_[4], ql_[4];
                    ldm4(kf0, kbase + (2 * c) * 640 + s * 32);
                    ldm4(kf1, kbase + (2 * c + 1) * 640 + s * 32);
                    ldm4(qh_, qbase + s * 32);
                    ldm4(ql_, qbase + 8960 + s * 32);   // QL region (+2240 words)
                    mma16816(Sp[0], qh_, kf0[0], kf0[1]);
                    mma16816(Sp[1], qh_, kf1[0], kf1[1]);
                    mma16816(Sp[0], qh_, kf0[2], kf0[3]);
                    mma16816(Sp[1], qh_, kf1[2], kf1[3]);
                    mma16816(Sp[0], ql_, kf0[0], kf0[1]);
                    mma16816(Sp[1], ql_, kf1[0], kf1[1]);
                }

                // ---- bias + mask + padding, then exp (no max subtract) ----
#pragma unroll
                for (int u = 0; u < 2; u++) {
                    int nt = 2 * c + u;
                    int c0 = nt * 8 + 2 * t;
                    bool cok = (c0 < NTOK);
                    if (rok0 && cok) {
                        float2 bb = __ldg((const float2*)(bmp + r0 * NTOK + c0));
                        Sp[u][0] += bb.x; Sp[u][1] += bb.y;
                    } else { Sp[u][0] = -1e30f; Sp[u][1] = -1e30f; }
                    if (rok1 && cok) {
                        float2 bb = __ldg((const float2*)(bmp + q1 * NTOK + c0));
                        Sp[u][2] += bb.x; Sp[u][3] += bb.y;
                    } else { Sp[u][2] = -1e30f; Sp[u][3] = -1e30f; }
                    Sp[u][0] = __expf(Sp[u][0]); s0 += Sp[u][0];
                    Sp[u][1] = __expf(Sp[u][1]); s0 += Sp[u][1];
                    Sp[u][2] = __expf(Sp[u][2]); s1 += Sp[u][2];
                    Sp[u][3] = __expf(Sp[u][3]); s1 += Sp[u][3];
                }

                // ---- pack unnormalized P to bf16 hi/lo A-fragment ----
                uint pah[4], pal[4];
                pah[0] = pkbf(Sp[0][0], Sp[0][1]);
                pal[0] = pkbf(Sp[0][0] - blo(pah[0]), Sp[0][1] - bhi(pah[0]));
                pah[1] = pkbf(Sp[0][2], Sp[0][3]);
                pal[1] = pkbf(Sp[0][2] - blo(pah[1]), Sp[0][3] - bhi(pah[1]));
                pah[2] = pkbf(Sp[1][0], Sp[1][1]);
                pal[2] = pkbf(Sp[1][0] - blo(pah[2]), Sp[1][1] - bhi(pah[2]));
                pah[3] = pkbf(Sp[1][2], Sp[1][3]);
                pal[3] = pkbf(Sp[1][2] - blo(pah[3]), Sp[1][3] - bhi(pah[3]));

                // ---- PV accumulate: 4 d-tiles (4 independent chains) ----
                uint vf[4][4];
#pragma unroll
                for (int nt = 0; nt < 4; nt++)
                    ldm4(vf[nt], vbase + nt * 1920 + c * 32);
#pragma unroll
                for (int nt = 0; nt < 4; nt++)
                    mma16816(&Oh[4 * nt], pah, vf[nt][0], vf[nt][1]);
#pragma unroll
                for (int nt = 0; nt < 4; nt++)
                    mma16816(&Oh[4 * nt], pah, vf[nt][2], vf[nt][3]);
#pragma unroll
                for (int nt = 0; nt < 4; nt++)
                    mma16816(&Oh[4 * nt], pal, vf[nt][0], vf[nt][1]);
            }

            // ---- deferred normalization + store O to smem (bf16 hi/lo) ----
            s0 += __shfl_xor_sync(0xffffffffu, s0, 1);
            s0 += __shfl_xor_sync(0xffffffffu, s0, 2);
            s1 += __shfl_xor_sync(0xffffffffu, s1, 1);
            s1 += __shfl_xor_sync(0xffffffffu, s1, 2);
            float inv0 = __frcp_rn(s0), inv1 = __frcp_rn(s1);

#pragma unroll
            for (int nt = 0; nt < 4; nt++) {
                int w = 16 * h + 4 * nt + t;
                if (rok0) {
                    float f0 = Oh[4 * nt + 0] * inv0, f1 = Oh[4 * nt + 1] * inv0;
                    uint hw_ = pkbf(f0, f1);
                    smw[OS + r0 * OSS + w]      = hw_;
                    smw[OS + r0 * OSS + 64 + w] = pkbf(f0 - blo(hw_), f1 - bhi(hw_));
                }
                if (rok1) {
                    float f2 = Oh[4 * nt + 2] * inv1, f3 = Oh[4 * nt + 3] * inv1;
                    uint hw_ = pkbf(f2, f3);
                    smw[OS + q1 * OSS + w]      = hw_;
                    smw[OS + q1 * OSS + 64 + w] = pkbf(f2 - blo(hw_), f3 - bhi(hw_));
                }
            }
        }
        __syncthreads();   // compute done before next head overwrites QKV
    }

    // ================= projection phase =================
    // W streamed in 2 chunks of 64 columns into the dead QKV region.
    const uint wcb = (uint)__cvta_generic_to_shared(
        smw + ((lane < 16) ? 0 : WCLO) + l7 * 68) + ((lane >> 3) & 1) * 16;
    float* orow0 = out + ((size_t)b * NTOK + r0) * DIMM;
    float* orow1 = out + ((size_t)b * NTOK + q1) * DIMM;

#pragma unroll
    for (int c2 = 0; c2 < 2; c2++) {
        // load + split W chunk: cols 64*c2 .. 64*c2+63
        for (int i = tid; i < 4096; i += 256) {
            int j = i >> 6, dp = i & 63;
            float2 w = *(const float2*)(pw + (size_t)(64 * c2 + j) * DIMM + 2 * dp);
            uint hw_ = pkbf(w.x, w.y);
            smw[j * 68 + dp]        = hw_;
            smw[WCLO + j * 68 + dp] = pkbf(w.x - blo(hw_), w.y - bhi(hw_));
        }
        __syncthreads();

        if (wid < 7) {
            float R[8][4];
#pragma unroll
            for (int i = 0; i < 8; i++)
#pragma unroll
                for (int j = 0; j < 4; j++) R[i][j] = 0.0f;

#pragma unroll
            for (int s = 0; s < 8; s++) {
                uint ah[4], al[4];
                ldm4(ah, abase + s * 32);
                ldm4(al, abase + 256 + s * 32);   // lo half (+64 words)
#pragma unroll
                for (int i = 0; i < 8; i++) {
                    uint wf[4];
                    ldm4(wf, wcb + i * 2176 + s * 32);
                    mma16816(R[i], ah, wf[0], wf[1]);
                    mma16816(R[i], ah, wf[2], wf[3]);
                    mma16816(R[i], al, wf[0], wf[1]);
                }
            }

#pragma unroll
            for (int i = 0; i < 8; i++) {
                int c0 = 64 * c2 + 8 * i + 2 * t;
                float2 bb = __ldg((const float2*)(pb + c0));
                if (rok0) {
                    float2 o0 = { R[i][0] + bb.x, R[i][1] + bb.y };
                    *(float2*)(orow0 + c0) = o0;
                }
                if (rok1) {
                    float2 o1 = { R[i][2] + bb.x, R[i][3] + bb.y };
                    *(float2*)(orow1 + c0) = o1;
                }
            }
        }
        __syncthreads();   // chunk compute done before next W load
    }
}

// ---------------------------------------------------------------------------
extern "C" void kernel_launch(void* const* d_in, const int* in_sizes, int n_in,
                              void* d_out, int out_size) {
    const float* x     = (const float*)d_in[0];
    const int*   rpi   = (const int*)d_in[1];      // int32 on the wire
    const float* mask  = (const float*)d_in[2];
    const float* table = (const float*)d_in[3];
    const float* pw    = (const float*)d_in[4];
    const float* pb    = (const float*)d_in[5];
    float*       out   = (float*)d_out;

    const int smem_fused = SMW_TOT * 4;   // 110336 B
    cudaFuncSetAttribute(fused_kernel, cudaFuncAttributeMaxDynamicSharedMemorySize, smem_fused);

    bm_kernel<<<(NWIN * NN + 255) / 256, 256>>>(rpi, table, mask);
    fused_kernel<<<B_WIN, 256, smem_fused>>>(x, pw, pb, out);
}

// round 13
// speedup vs baseline: 1.1398x; 1.0953x over previous
#include <cuda_runtime.h>

#define B_WIN 2048
#define NTOK  98
#define NHEAD 4
#define HD    32
#define C3    384
#define DIMM  128
#define NWIN  64
#define NN    (NTOK * NTOK)   // 9604
#define RPB_ROWS 507
#define NKP   49              // packed k-pairs per row

typedef unsigned int uint;

// ---------------- bf16 helpers ----------------
__device__ __forceinline__ uint pkbf(float lo, float hi) {
    uint r; asm("cvt.rn.bf16x2.f32 %0, %1, %2;" : "=r"(r) : "f"(hi), "f"(lo)); return r;
}
__device__ __forceinline__ float blo(uint p) { return __uint_as_float(p << 16); }
__device__ __forceinline__ float bhi(uint p) { return __uint_as_float(p & 0xffff0000u); }

// D += A * B  (m16n8k16, bf16 in, f32 accum)
__device__ __forceinline__ void mma16816(float* d, const uint* a, uint b0, uint b1) {
    asm("mma.sync.aligned.m16n8k16.row.col.f32.bf16.bf16.f32 "
        "{%0,%1,%2,%3}, {%4,%5,%6,%7}, {%8,%9}, {%0,%1,%2,%3};"
        : "+f"(d[0]), "+f"(d[1]), "+f"(d[2]), "+f"(d[3])
        : "r"(a[0]), "r"(a[1]), "r"(a[2]), "r"(a[3]), "r"(b0), "r"(b1));
}

// ldmatrix x4 (non-transposed)
__device__ __forceinline__ void ldm4(uint* d, uint addr) {
    asm volatile("ldmatrix.sync.aligned.m8n8.x4.shared.b16 {%0,%1,%2,%3}, [%4];"
        : "=r"(d[0]), "=r"(d[1]), "=r"(d[2]), "=r"(d[3]) : "r"(addr));
}
// ldmatrix x4 transposed (b16)
__device__ __forceinline__ void ldm4t(uint* d, uint addr) {
    asm volatile("ldmatrix.sync.aligned.m8n8.x4.trans.shared.b16 {%0,%1,%2,%3}, [%4];"
        : "=r"(d[0]), "=r"(d[1]), "=r"(d[2]), "=r"(d[3]) : "r"(addr));
}

// ---------------- scratch ----------------
__device__ uint g_bmh[(size_t)NWIN * NHEAD * NTOK * NKP];   // bias+mask bf16x2, 4.9 MB

// smem word offsets, attention phase
#define QH  0
#define QL  2240
#define KH  4480
#define KL  6720
#define VH  8960
#define VL  11200
#define QKVW 13440
// O buffer (persists): 112 rows x 132-word stride; hi words 0-63, lo words 64-127
#define OS  13440
#define OSS 132
#define SMW_TOT (OS + 112 * OSS)   // 28224 words = 112896 B
// projection W chunk overlays QKV region
#define WCLO 4352

// ---------------------------------------------------------------------------
// Kernel A: pack bias+mask to bf16x2:
//   g_bmh[w][h][q][kp] = (table[rpi[q,2kp]][h]+mask[w,q,2kp],
//                         table[rpi[q,2kp+1]][h]+mask[w,q,2kp+1])
// ---------------------------------------------------------------------------
__global__ void bm_kernel(const int* __restrict__ rpi,
                          const float* __restrict__ table,
                          const float* __restrict__ mask) {
    int i = blockIdx.x * blockDim.x + threadIdx.x;
    if (i >= NWIN * NTOK * NKP) return;
    int w = i / (NTOK * NKP);
    int e = i - w * (NTOK * NKP);
    int q = e / NKP;
    int kp = e - q * NKP;
    int k0 = 2 * kp, k1 = 2 * kp + 1;
    int r0 = rpi[q * NTOK + k0];
    int r1 = rpi[q * NTOK + k1];
    r0 = (r0 < 0) ? 0 : (r0 >= RPB_ROWS ? RPB_ROWS - 1 : r0);
    r1 = (r1 < 0) ? 0 : (r1 >= RPB_ROWS ? RPB_ROWS - 1 : r1);
    float mk0 = mask[(size_t)w * NN + q * NTOK + k0];
    float mk1 = mask[(size_t)w * NN + q * NTOK + k1];
#pragma unroll
    for (int hh = 0; hh < NHEAD; hh++) {
        float v0 = table[r0 * NHEAD + hh] + mk0;
        float v1 = table[r1 * NHEAD + hh] + mk1;
        g_bmh[(((size_t)w * NHEAD + hh) * NTOK + q) * NKP + kp] = pkbf(v0, v1);
    }
}

// ---------------------------------------------------------------------------
// Fused: per window. 4 heads of streaming attention (O -> smem bf16 hi/lo),
// then projection from smem via LDSM, W streamed in 2 column chunks.
// 256 threads, 8 warps (warps 0-6 compute; warp 7 load/barrier only).
// ---------------------------------------------------------------------------
__global__ __launch_bounds__(256, 2) void fused_kernel(const float* __restrict__ x,
                                                       const float* __restrict__ pw,
                                                       const float* __restrict__ pb,
                                                       float* __restrict__ out) {
    extern __shared__ uint smw[];

    const int b   = blockIdx.x;
    const int tid = threadIdx.x;
    const int lane = tid & 31;
    const int wid  = tid >> 5;
    const int g = lane >> 2;
    const int t = lane & 3;
    const int l7 = lane & 7;

    const float scale = 0.17677669529663687f;  // 1/sqrt(32)
    const float* xb = x + (size_t)b * NTOK * C3;
    const int r0 = wid * 16 + g;
    const int q1 = r0 + 8;
    const bool rok0 = (r0 < NTOK), rok1 = (q1 < NTOK);

    // ---- per-lane ldmatrix base addresses ----
    const uint qbase = (uint)__cvta_generic_to_shared(
        smw + QH + (wid * 16 + ((lane >> 3) & 1) * 8 + l7) * 20) + (lane >> 4) * 16;
    const uint kbase = (uint)__cvta_generic_to_shared(
        smw + ((lane < 16) ? KH : KL) + l7 * 20) + ((lane >> 3) & 1) * 16;
    // V (trans): m0/m1 = hi k-halves, m2/m3 = lo k-halves; rows are tokens
    const uint vtb = (uint)__cvta_generic_to_shared(
        smw + ((lane < 16) ? VH : VL) + l7 * 20) + ((lane >> 3) & 1) * 640;
    // A fragments from Os (projection): hi at +0, lo at +256 bytes
    const uint abase = (uint)__cvta_generic_to_shared(
        smw + OS + (wid * 16 + ((lane >> 3) & 1) * 8 + l7) * OSS) + (lane >> 4) * 16;

    // ---- zero everything once (QKV pads + Os invalid rows) ----
    for (int i = tid; i < SMW_TOT; i += 256) smw[i] = 0u;
    __syncthreads();

#pragma unroll
    for (int h = 0; h < NHEAD; h++) {
        // ---- load + split Q(scaled), K, V to bf16 hi/lo (all row-major) ----
        for (int i = tid; i < NTOK * 16; i += 256) {
            int q = i >> 4, dp = i & 15;
            const float* base = xb + q * C3 + h * HD + 2 * dp;
            float2 qv = *(const float2*)base;
            qv.x *= scale; qv.y *= scale;
            uint hq = pkbf(qv.x, qv.y);
            smw[QH + q * 20 + dp] = hq;
            smw[QL + q * 20 + dp] = pkbf(qv.x - blo(hq), qv.y - bhi(hq));
            float2 kv = *(const float2*)(base + DIMM);
            uint hk = pkbf(kv.x, kv.y);
            smw[KH + q * 20 + dp] = hk;
            smw[KL + q * 20 + dp] = pkbf(kv.x - blo(hk), kv.y - bhi(hk));
            float2 vv = *(const float2*)(base + 2 * DIMM);
            uint hv = pkbf(vv.x, vv.y);
            smw[VH + q * 20 + dp] = hv;
            smw[VL + q * 20 + dp] = pkbf(vv.x - blo(hv), vv.y - bhi(hv));
        }
        __syncthreads();

        if (wid < 7) {
            // ---- Q fragments hoisted: both k-steps, hi+lo ----
            uint qfh[2][4], qfl[2][4];
#pragma unroll
            for (int s = 0; s < 2; s++) {
                ldm4(qfh[s], qbase + s * 32);
                ldm4(qfl[s], qbase + 8960 + s * 32);   // QL region (+2240 words)
            }

            const uint* bmp = g_bmh + ((size_t)(b & (NWIN - 1)) * NHEAD + h) * NTOK * NKP;
            float s0 = 0.0f, s1 = 0.0f;
            float Oh[16];
#pragma unroll
            for (int j = 0; j < 16; j++) Oh[j] = 0.0f;

            // ---- stream over k16 chunks: S pair -> exp -> pack -> PV ----
#pragma unroll
            for (int c = 0; c < 7; c++) {
                float Sp[2][4];
#pragma unroll
                for (int u = 0; u < 2; u++)
#pragma unroll
                    for (int j = 0; j < 4; j++) Sp[u][j] = 0.0f;

#pragma unroll
                for (int s = 0; s < 2; s++) {
                    uint kf0[4], kf1[4];
                    ldm4(kf0, kbase + (2 * c) * 640 + s * 32);
                    ldm4(kf1, kbase + (2 * c + 1) * 640 + s * 32);
                    mma16816(Sp[0], qfh[s], kf0[0], kf0[1]);
                    mma16816(Sp[1], qfh[s], kf1[0], kf1[1]);
                    mma16816(Sp[0], qfh[s], kf0[2], kf0[3]);
                    mma16816(Sp[1], qfh[s], kf1[2], kf1[3]);
                    mma16816(Sp[0], qfl[s], kf0[0], kf0[1]);
                    mma16816(Sp[1], qfl[s], kf1[0], kf1[1]);
                }

                // ---- bias (bf16x2) + padding, then exp (no max subtract) ----
#pragma unroll
                for (int u = 0; u < 2; u++) {
                    int nt = 2 * c + u;
                    int c0 = nt * 8 + 2 * t;
                    bool cok = (c0 < NTOK);
                    if (rok0 && cok) {
                        uint bp = __ldg(bmp + r0 * NKP + nt * 4 + t);
                        Sp[u][0] += blo(bp); Sp[u][1] += bhi(bp);
                    } else { Sp[u][0] = -1e30f; Sp[u][1] = -1e30f; }
                    if (rok1 && cok) {
                        uint bp = __ldg(bmp + q1 * NKP + nt * 4 + t);
                        Sp[u][2] += blo(bp); Sp[u][3] += bhi(bp);
                    } else { Sp[u][2] = -1e30f; Sp[u][3] = -1e30f; }
                    Sp[u][0] = __expf(Sp[u][0]); s0 += Sp[u][0];
                    Sp[u][1] = __expf(Sp[u][1]); s0 += Sp[u][1];
                    Sp[u][2] = __expf(Sp[u][2]); s1 += Sp[u][2];
                    Sp[u][3] = __expf(Sp[u][3]); s1 += Sp[u][3];
                }

                // ---- pack unnormalized P to bf16 hi/lo A-fragment ----
                uint pah[4], pal[4];
                pah[0] = pkbf(Sp[0][0], Sp[0][1]);
                pal[0] = pkbf(Sp[0][0] - blo(pah[0]), Sp[0][1] - bhi(pah[0]));
                pah[1] = pkbf(Sp[0][2], Sp[0][3]);
                pal[1] = pkbf(Sp[0][2] - blo(pah[1]), Sp[0][3] - bhi(pah[1]));
                pah[2] = pkbf(Sp[1][0], Sp[1][1]);
                pal[2] = pkbf(Sp[1][0] - blo(pah[2]), Sp[1][1] - bhi(pah[2]));
                pah[3] = pkbf(Sp[1][2], Sp[1][3]);
                pal[3] = pkbf(Sp[1][2] - blo(pah[3]), Sp[1][3] - bhi(pah[3]));

                // ---- PV accumulate: 4 d-tiles via ldmatrix.trans of V ----
                uint vf[4][4];
#pragma unroll
                for (int nt = 0; nt < 4; nt++)
                    ldm4t(vf[nt], vtb + c * 1280 + nt * 16);
#pragma unroll
                for (int nt = 0; nt < 4; nt++)
                    mma16816(&Oh[4 * nt], pah, vf[nt][0], vf[nt][1]);
#pragma unroll
                for (int nt = 0; nt < 4; nt++)
                    mma16816(&Oh[4 * nt], pah, vf[nt][2], vf[nt][3]);
#pragma unroll
                for (int nt = 0; nt < 4; nt++)
                    mma16816(&Oh[4 * nt], pal, vf[nt][0], vf[nt][1]);
            }

            // ---- deferred normalization + store O to smem (bf16 hi/lo) ----
            s0 += __shfl_xor_sync(0xffffffffu, s0, 1);
            s0 += __shfl_xor_sync(0xffffffffu, s0, 2);
            s1 += __shfl_xor_sync(0xffffffffu, s1, 1);
            s1 += __shfl_xor_sync(0xffffffffu, s1, 2);
            float inv0 = __frcp_rn(s0), inv1 = __frcp_rn(s1);

#pragma unroll
            for (int nt = 0; nt < 4; nt++) {
                int w = 16 * h + 4 * nt + t;
                if (rok0) {
                    float f0 = Oh[4 * nt + 0] * inv0, f1 = Oh[4 * nt + 1] * inv0;
                    uint hw_ = pkbf(f0, f1);
                    smw[OS + r0 * OSS + w]      = hw_;
                    smw[OS + r0 * OSS + 64 + w] = pkbf(f0 - blo(hw_), f1 - bhi(hw_));
                }
                if (rok1) {
                    float f2 = Oh[4 * nt + 2] * inv1, f3 = Oh[4 * nt + 3] * inv1;
                    uint hw_ = pkbf(f2, f3);
                    smw[OS + q1 * OSS + w]      = hw_;
                    smw[OS + q1 * OSS + 64 + w] = pkbf(f2 - blo(hw_), f3 - bhi(hw_));
                }
            }
        }
        __syncthreads();   // compute done before next head overwrites QKV
    }

    // ================= projection phase =================
    const uint wcb = (uint)__cvta_generic_to_shared(
        smw + ((lane < 16) ? 0 : WCLO) + l7 * 68) + ((lane >> 3) & 1) * 16;
    float* orow0 = out + ((size_t)b * NTOK + r0) * DIMM;
    float* orow1 = out + ((size_t)b * NTOK + q1) * DIMM;

#pragma unroll
    for (int c2 = 0; c2 < 2; c2++) {
        // load + split W chunk: cols 64*c2 .. 64*c2+63
        for (int i = tid; i < 4096; i += 256) {
            int j = i >> 6, dp = i & 63;
            float2 w = *(const float2*)(pw + (size_t)(64 * c2 + j) * DIMM + 2 * dp);
            uint hw_ = pkbf(w.x, w.y);
            smw[j * 68 + dp]        = hw_;
            smw[WCLO + j * 68 + dp] = pkbf(w.x - blo(hw_), w.y - bhi(hw_));
        }
        __syncthreads();

        if (wid < 7) {
            float R[8][4];
#pragma unroll
            for (int i = 0; i < 8; i++)
#pragma unroll
                for (int j = 0; j < 4; j++) R[i][j] = 0.0f;

#pragma unroll
            for (int s = 0; s < 8; s++) {
                uint ah[4], al[4];
                ldm4(ah, abase + s * 32);
                ldm4(al, abase + 256 + s * 32);   // lo half (+64 words)
#pragma unroll
                for (int i = 0; i < 8; i++) {
                    uint wf[4];
                    ldm4(wf, wcb + i * 2176 + s * 32);
                    mma16816(R[i], ah, wf[0], wf[1]);
                    mma16816(R[i], ah, wf[2], wf[3]);
                    mma16816(R[i], al, wf[0], wf[1]);
                }
            }

#pragma unroll
            for (int i = 0; i < 8; i++) {
                int c0 = 64 * c2 + 8 * i + 2 * t;
                float2 bb = __ldg((const float2*)(pb + c0));
                if (rok0) {
                    float2 o0 = { R[i][0] + bb.x, R[i][1] + bb.y };
                    *(float2*)(orow0 + c0) = o0;
                }
                if (rok1) {
                    float2 o1 = { R[i][2] + bb.x, R[i][3] + bb.y };
                    *(float2*)(orow1 + c0) = o1;
                }
            }
        }
        __syncthreads();   // chunk compute done before next W load
    }
}

// ---------------------------------------------------------------------------
extern "C" void kernel_launch(void* const* d_in, const int* in_sizes, int n_in,
                              void* d_out, int out_size) {
    const float* x     = (const float*)d_in[0];
    const int*   rpi   = (const int*)d_in[1];      // int32 on the wire
    const float* mask  = (const float*)d_in[2];
    const float* table = (const float*)d_in[3];
    const float* pw    = (const float*)d_in[4];
    const float* pb    = (const float*)d_in[5];
    float*       out   = (float*)d_out;

    const int smem_fused = SMW_TOT * 4;   // 112896 B
    cudaFuncSetAttribute(fused_kernel, cudaFuncAttributeMaxDynamicSharedMemorySize, smem_fused);

    bm_kernel<<<(NWIN * NTOK * NKP + 255) / 256, 256>>>(rpi, table, mask);
    fused_kernel<<<B_WIN, 256, smem_fused>>>(x, pw, pb, out);
}

// round 16
// speedup vs baseline: 1.2805x; 1.1234x over previous
#include <cuda_runtime.h>

#define B_WIN 2048
#define NTOK  98
#define NHEAD 4
#define HD    32
#define C3    384
#define DIMM  128
#define NWIN  64
#define NN    (NTOK * NTOK)   // 9604
#define RPB_ROWS 507
#define NKP   49              // packed k-pairs per row

typedef unsigned int uint;

// ---------------- bf16 helpers ----------------
__device__ __forceinline__ uint pkbf(float lo, float hi) {
    uint r; asm("cvt.rn.bf16x2.f32 %0, %1, %2;" : "=r"(r) : "f"(hi), "f"(lo)); return r;
}
__device__ __forceinline__ float blo(uint p) { return __uint_as_float(p << 16); }
__device__ __forceinline__ float bhi(uint p) { return __uint_as_float(p & 0xffff0000u); }
__device__ __forceinline__ float ex2f(float x) {
    float r; asm("ex2.approx.f32 %0, %1;" : "=f"(r) : "f"(x)); return r;
}

// D += A * B  (m16n8k16, bf16 in, f32 accum)
__device__ __forceinline__ void mma16816(float* d, const uint* a, uint b0, uint b1) {
    asm("mma.sync.aligned.m16n8k16.row.col.f32.bf16.bf16.f32 "
        "{%0,%1,%2,%3}, {%4,%5,%6,%7}, {%8,%9}, {%0,%1,%2,%3};"
        : "+f"(d[0]), "+f"(d[1]), "+f"(d[2]), "+f"(d[3])
        : "r"(a[0]), "r"(a[1]), "r"(a[2]), "r"(a[3]), "r"(b0), "r"(b1));
}

// ldmatrix x4 (non-transposed / transposed)
__device__ __forceinline__ void ldm4(uint* d, uint addr) {
    asm volatile("ldmatrix.sync.aligned.m8n8.x4.shared.b16 {%0,%1,%2,%3}, [%4];"
        : "=r"(d[0]), "=r"(d[1]), "=r"(d[2]), "=r"(d[3]) : "r"(addr));
}
__device__ __forceinline__ void ldm4t(uint* d, uint addr) {
    asm volatile("ldmatrix.sync.aligned.m8n8.x4.trans.shared.b16 {%0,%1,%2,%3}, [%4];"
        : "=r"(d[0]), "=r"(d[1]), "=r"(d[2]), "=r"(d[3]) : "r"(addr));
}

#define NEGINF2 0xFF80FF80u   // bf16x2 (-inf, -inf)

// ---------------- scratch ----------------
__device__ uint g_bmh[(size_t)NWIN * NHEAD * NTOK * NKP];   // (bias+mask)*log2e bf16x2

// smem word offsets, attention phase
#define QH  0
#define QL  2240
#define KH  4480
#define KL  6720
#define VH  8960
#define VL  11200
#define QKVW 13440
// O buffer (persists): 112 rows x 132-word stride; hi words 0-63, lo words 64-127
#define OS  13440
#define OSS 132
#define SMW_TOT (OS + 112 * OSS)   // 28224 words = 112896 B
// projection W chunk overlays QKV region
#define WCLO 4352

// ---------------------------------------------------------------------------
// Kernel A: pack (bias+mask)*log2e to bf16x2 pairs along k.
// ---------------------------------------------------------------------------
__global__ void bm_kernel(const int* __restrict__ rpi,
                          const float* __restrict__ table,
                          const float* __restrict__ mask) {
    const float L2E = 1.4426950408889634f;
    int i = blockIdx.x * blockDim.x + threadIdx.x;
    if (i >= NWIN * NTOK * NKP) return;
    int w = i / (NTOK * NKP);
    int e = i - w * (NTOK * NKP);
    int q = e / NKP;
    int kp = e - q * NKP;
    int k0 = 2 * kp, k1 = 2 * kp + 1;
    int r0 = rpi[q * NTOK + k0];
    int r1 = rpi[q * NTOK + k1];
    r0 = (r0 < 0) ? 0 : (r0 >= RPB_ROWS ? RPB_ROWS - 1 : r0);
    r1 = (r1 < 0) ? 0 : (r1 >= RPB_ROWS ? RPB_ROWS - 1 : r1);
    float mk0 = mask[(size_t)w * NN + q * NTOK + k0];
    float mk1 = mask[(size_t)w * NN + q * NTOK + k1];
#pragma unroll
    for (int hh = 0; hh < NHEAD; hh++) {
        float v0 = (table[r0 * NHEAD + hh] + mk0) * L2E;
        float v1 = (table[r1 * NHEAD + hh] + mk1) * L2E;
        g_bmh[(((size_t)w * NHEAD + hh) * NTOK + q) * NKP + kp] = pkbf(v0, v1);
    }
}

// ---------------------------------------------------------------------------
// Fused: per window. 4 heads of streaming attention (O -> smem bf16 hi/lo),
// then projection from smem via LDSM, W streamed in 2 column chunks.
// 256 threads, 8 warps (warps 0-6 compute; warp 7 load/barrier only).
// ---------------------------------------------------------------------------
__global__ __launch_bounds__(256, 2) void fused_kernel(const float* __restrict__ x,
                                                       const float* __restrict__ pw,
                                                       const float* __restrict__ pb,
                                                       float* __restrict__ out) {
    extern __shared__ uint smw[];

    const int b   = blockIdx.x;
    const int tid = threadIdx.x;
    const int lane = tid & 31;
    const int wid  = tid >> 5;
    const int g = lane >> 2;
    const int t = lane & 3;
    const int l7 = lane & 7;

    // scale folds 1/sqrt(hd) AND log2e (softmax via ex2)
    const float scale = 0.17677669529663687f * 1.4426950408889634f;
    const float* xb = x + (size_t)b * NTOK * C3;
    const int r0 = wid * 16 + g;
    const int q1 = r0 + 8;
    const bool rok0 = (r0 < NTOK), rok1 = (q1 < NTOK);

    // ---- per-lane ldmatrix base addresses ----
    const uint qbase = (uint)__cvta_generic_to_shared(
        smw + QH + (wid * 16 + ((lane >> 3) & 1) * 8 + l7) * 20) + (lane >> 4) * 16;
    const uint kbase = (uint)__cvta_generic_to_shared(
        smw + ((lane < 16) ? KH : KL) + l7 * 20) + ((lane >> 3) & 1) * 16;
    const uint vtb = (uint)__cvta_generic_to_shared(
        smw + ((lane < 16) ? VH : VL) + l7 * 20) + ((lane >> 3) & 1) * 640;
    const uint abase = (uint)__cvta_generic_to_shared(
        smw + OS + (wid * 16 + ((lane >> 3) & 1) * 8 + l7) * OSS) + (lane >> 4) * 16;

    // ---- zero everything once (QKV pads + Os invalid rows) ----
    for (int i = tid; i < SMW_TOT; i += 256) smw[i] = 0u;
    __syncthreads();

#pragma unroll
    for (int h = 0; h < NHEAD; h++) {
        // ---- load + split Q(scaled), K, V to bf16 hi/lo (float4 / STS.64) ----
        for (int i = tid; i < NTOK * 8; i += 256) {
            int q = i >> 3, dp4 = i & 7;            // dp4: float4 index within 32 floats
            const float4* base = (const float4*)(xb + q * C3 + h * HD) + dp4;
            float4 qv = base[0];
            qv.x *= scale; qv.y *= scale; qv.z *= scale; qv.w *= scale;
            uint h0 = pkbf(qv.x, qv.y), h1 = pkbf(qv.z, qv.w);
            *(uint2*)(smw + QH + q * 20 + 2 * dp4) = make_uint2(h0, h1);
            *(uint2*)(smw + QL + q * 20 + 2 * dp4) = make_uint2(
                pkbf(qv.x - blo(h0), qv.y - bhi(h0)),
                pkbf(qv.z - blo(h1), qv.w - bhi(h1)));
            float4 kv = base[DIMM / 4];
            uint k0 = pkbf(kv.x, kv.y), k1 = pkbf(kv.z, kv.w);
            *(uint2*)(smw + KH + q * 20 + 2 * dp4) = make_uint2(k0, k1);
            *(uint2*)(smw + KL + q * 20 + 2 * dp4) = make_uint2(
                pkbf(kv.x - blo(k0), kv.y - bhi(k0)),
                pkbf(kv.z - blo(k1), kv.w - bhi(k1)));
            float4 vv = base[2 * DIMM / 4];
            uint v0 = pkbf(vv.x, vv.y), v1 = pkbf(vv.z, vv.w);
            *(uint2*)(smw + VH + q * 20 + 2 * dp4) = make_uint2(v0, v1);
            *(uint2*)(smw + VL + q * 20 + 2 * dp4) = make_uint2(
                pkbf(vv.x - blo(v0), vv.y - bhi(v0)),
                pkbf(vv.z - blo(v1), vv.w - bhi(v1)));
        }
        __syncthreads();

        if (wid < 7) {
            // ---- Q fragments hoisted: both k-steps, hi+lo ----
            uint qfh[2][4], qfl[2][4];
#pragma unroll
            for (int s = 0; s < 2; s++) {
                ldm4(qfh[s], qbase + s * 32);
                ldm4(qfl[s], qbase + 8960 + s * 32);   // QL region (+2240 words)
            }

            const uint* bmp = g_bmh + ((size_t)(b & (NWIN - 1)) * NHEAD + h) * NTOK * NKP;
            const uint* bmr0 = bmp + r0 * NKP + t;
            const uint* bmq1 = bmp + q1 * NKP + t;
            float s0 = 0.0f, s1 = 0.0f;
            float Oh[16];
#pragma unroll
            for (int j = 0; j < 16; j++) Oh[j] = 0.0f;

            // bias prefetch (chunk 0); invalid -> -inf pair (masks via ex2->0)
            uint bw[4];
#pragma unroll
            for (int u = 0; u < 2; u++) {
                bool cok = (u * 8 + 2 * t) < NTOK;
                bw[2 * u]     = (rok0 && cok) ? __ldg(bmr0 + u * 4) : NEGINF2;
                bw[2 * u + 1] = (rok1 && cok) ? __ldg(bmq1 + u * 4) : NEGINF2;
            }

            // ---- stream over k16 chunks: S pair -> ex2 -> pack -> PV ----
#pragma unroll
            for (int c = 0; c < 7; c++) {
                // prefetch bias for next chunk
                uint bwn[4];
                if (c < 6) {
#pragma unroll
                    for (int u = 0; u < 2; u++) {
                        int nt = 2 * (c + 1) + u;
                        bool cok = (nt * 8 + 2 * t) < NTOK;
                        bwn[2 * u]     = (rok0 && cok) ? __ldg(bmr0 + nt * 4) : NEGINF2;
                        bwn[2 * u + 1] = (rok1 && cok) ? __ldg(bmq1 + nt * 4) : NEGINF2;
                    }
                }

                float Sp[2][4];
#pragma unroll
                for (int u = 0; u < 2; u++)
#pragma unroll
                    for (int j = 0; j < 4; j++) Sp[u][j] = 0.0f;

#pragma unroll
                for (int s = 0; s < 2; s++) {
                    uint kf0[4], kf1[4];
                    ldm4(kf0, kbase + (2 * c) * 640 + s * 32);
                    ldm4(kf1, kbase + (2 * c + 1) * 640 + s * 32);
                    mma16816(Sp[0], qfh[s], kf0[0], kf0[1]);
                    mma16816(Sp[1], qfh[s], kf1[0], kf1[1]);
                    mma16816(Sp[0], qfh[s], kf0[2], kf0[3]);
                    mma16816(Sp[1], qfh[s], kf1[2], kf1[3]);
                    mma16816(Sp[0], qfl[s], kf0[0], kf0[1]);
                    mma16816(Sp[1], qfl[s], kf1[0], kf1[1]);
                }

                // ---- bias add + ex2 (logits pre-scaled by log2e) ----
#pragma unroll
                for (int u = 0; u < 2; u++) {
                    Sp[u][0] = ex2f(Sp[u][0] + blo(bw[2 * u]));     s0 += Sp[u][0];
                    Sp[u][1] = ex2f(Sp[u][1] + bhi(bw[2 * u]));     s0 += Sp[u][1];
                    Sp[u][2] = ex2f(Sp[u][2] + blo(bw[2 * u + 1])); s1 += Sp[u][2];
                    Sp[u][3] = ex2f(Sp[u][3] + bhi(bw[2 * u + 1])); s1 += Sp[u][3];
                }
#pragma unroll
                for (int j = 0; j < 4; j++) bw[j] = bwn[j];

                // ---- pack unnormalized P to bf16 hi/lo A-fragment ----
                uint pah[4], pal[4];
                pah[0] = pkbf(Sp[0][0], Sp[0][1]);
                pal[0] = pkbf(Sp[0][0] - blo(pah[0]), Sp[0][1] - bhi(pah[0]));
                pah[1] = pkbf(Sp[0][2], Sp[0][3]);
                pal[1] = pkbf(Sp[0][2] - blo(pah[1]), Sp[0][3] - bhi(pah[1]));
                pah[2] = pkbf(Sp[1][0], Sp[1][1]);
                pal[2] = pkbf(Sp[1][0] - blo(pah[2]), Sp[1][1] - bhi(pah[2]));
                pah[3] = pkbf(Sp[1][2], Sp[1][3]);
                pal[3] = pkbf(Sp[1][2] - blo(pah[3]), Sp[1][3] - bhi(pah[3]));

                // ---- PV accumulate: 4 d-tiles via ldmatrix.trans of V ----
                uint vf[4][4];
#pragma unroll
                for (int nt = 0; nt < 4; nt++)
                    ldm4t(vf[nt], vtb + c * 1280 + nt * 16);
#pragma unroll
                for (int nt = 0; nt < 4; nt++)
                    mma16816(&Oh[4 * nt], pah, vf[nt][0], vf[nt][1]);
#pragma unroll
                for (int nt = 0; nt < 4; nt++)
                    mma16816(&Oh[4 * nt], pah, vf[nt][2], vf[nt][3]);
#pragma unroll
                for (int nt = 0; nt < 4; nt++)
                    mma16816(&Oh[4 * nt], pal, vf[nt][0], vf[nt][1]);
            }

            // ---- deferred normalization + store O to smem (bf16 hi/lo) ----
            s0 += __shfl_xor_sync(0xffffffffu, s0, 1);
            s0 += __shfl_xor_sync(0xffffffffu, s0, 2);
            s1 += __shfl_xor_sync(0xffffffffu, s1, 1);
            s1 += __shfl_xor_sync(0xffffffffu, s1, 2);
            float inv0 = __frcp_rn(s0), inv1 = __frcp_rn(s1);

#pragma unroll
            for (int nt = 0; nt < 4; nt++) {
                int w = 16 * h + 4 * nt + t;
                if (rok0) {
                    float f0 = Oh[4 * nt + 0] * inv0, f1 = Oh[4 * nt + 1] * inv0;
                    uint hw_ = pkbf(f0, f1);
                    smw[OS + r0 * OSS + w]      = hw_;
                    smw[OS + r0 * OSS + 64 + w] = pkbf(f0 - blo(hw_), f1 - bhi(hw_));
                }
                if (rok1) {
                    float f2 = Oh[4 * nt + 2] * inv1, f3 = Oh[4 * nt + 3] * inv1;
                    uint hw_ = pkbf(f2, f3);
                    smw[OS + q1 * OSS + w]      = hw_;
                    smw[OS + q1 * OSS + 64 + w] = pkbf(f2 - blo(hw_), f3 - bhi(hw_));
                }
            }
        }
        __syncthreads();   // compute done before next head overwrites QKV
    }

    // ================= projection phase =================
    const uint wcb = (uint)__cvta_generic_to_shared(
        smw + ((lane < 16) ? 0 : WCLO) + l7 * 68) + ((lane >> 3) & 1) * 16;
    float* orow0 = out + ((size_t)b * NTOK + r0) * DIMM;
    float* orow1 = out + ((size_t)b * NTOK + q1) * DIMM;

#pragma unroll
    for (int c2 = 0; c2 < 2; c2++) {
        // load + split W chunk (float4): cols 64*c2 .. 64*c2+63
        for (int i = tid; i < 2048; i += 256) {
            int j = i >> 5, dp4 = i & 31;
            float4 w = *((const float4*)(pw + (size_t)(64 * c2 + j) * DIMM) + dp4);
            uint h0 = pkbf(w.x, w.y), h1 = pkbf(w.z, w.w);
            *(uint2*)(smw + j * 68 + 2 * dp4) = make_uint2(h0, h1);
            *(uint2*)(smw + WCLO + j * 68 + 2 * dp4) = make_uint2(
                pkbf(w.x - blo(h0), w.y - bhi(h0)),
                pkbf(w.z - blo(h1), w.w - bhi(h1)));
        }
        __syncthreads();

        if (wid < 7) {
            float R[8][4];
#pragma unroll
            for (int i = 0; i < 8; i++)
#pragma unroll
                for (int j = 0; j < 4; j++) R[i][j] = 0.0f;

#pragma unroll
            for (int s = 0; s < 8; s++) {
                uint ah[4], al[4];
                ldm4(ah, abase + s * 32);
                ldm4(al, abase + 256 + s * 32);   // lo half (+64 words)
#pragma unroll
                for (int i = 0; i < 8; i++) {
                    uint wf[4];
                    ldm4(wf, wcb + i * 2176 + s * 32);
                    mma16816(R[i], ah, wf[0], wf[1]);
                    mma16816(R[i], ah, wf[2], wf[3]);
                    mma16816(R[i], al, wf[0], wf[1]);
                }
            }

#pragma unroll
            for (int i = 0; i < 8; i++) {
                int c0 = 64 * c2 + 8 * i + 2 * t;
                float2 bb = __ldg((const float2*)(pb + c0));
                if (rok0) {
                    float2 o0 = { R[i][0] + bb.x, R[i][1] + bb.y };
                    *(float2*)(orow0 + c0) = o0;
                }
                if (rok1) {
                    float2 o1 = { R[i][2] + bb.x, R[i][3] + bb.y };
                    *(float2*)(orow1 + c0) = o1;
                }
            }
        }
        __syncthreads();   // chunk compute done before next W load
    }
}

// ---------------------------------------------------------------------------
extern "C" void kernel_launch(void* const* d_in, const int* in_sizes, int n_in,
                              void* d_out, int out_size) {
    const float* x     = (const float*)d_in[0];
    const int*   rpi   = (const int*)d_in[1];      // int32 on the wire
    const float* mask  = (const float*)d_in[2];
    const float* table = (const float*)d_in[3];
    const float* pw    = (const float*)d_in[4];
    const float* pb    = (const float*)d_in[5];
    float*       out   = (float*)d_out;

    const int smem_fused = SMW_TOT * 4;   // 112896 B
    cudaFuncSetAttribute(fused_kernel, cudaFuncAttributeMaxDynamicSharedMemorySize, smem_fused);

    bm_kernel<<<(NWIN * NTOK * NKP + 255) / 256, 256>>>(rpi, table, mask);
    fused_kernel<<<B_WIN, 256, smem_fused>>>(x, pw, pb, out);
}